// round 4
// baseline (speedup 1.0000x reference)
#include <cuda_runtime.h>

// LoRALayerNorm: y = ((x - mean) * rsqrt(var + eps)) * scale + shift
//   scale[i] = SCALING * sum_r sA[i,r] * sB[r,i]
//   shift[i] = SCALING * sum_r hA[i,r] * hB[r,i]
// Shapes: x [2,4096,8192] fp32; A [8192,4]; B [4,8192]. SCALING = 8/4 = 2.

#define N_FEAT 8192
#define RANK   4
#define TPB    256
#define V4T    (N_FEAT / 4 / TPB)   // 8 float4 per thread
#define NWARPS (TPB / 32)           // 8
#define EPS_LN 1e-5f

__device__ float g_scale[N_FEAT];
__device__ float g_shift[N_FEAT];

__global__ void compute_scales_kernel(const float* __restrict__ sA,
                                      const float* __restrict__ sB,
                                      const float* __restrict__ hA,
                                      const float* __restrict__ hB) {
    int i = blockIdx.x * blockDim.x + threadIdx.x;
    if (i < N_FEAT) {
        float s = 0.f, h = 0.f;
#pragma unroll
        for (int r = 0; r < RANK; r++) {
            s = fmaf(sA[i * RANK + r], sB[r * N_FEAT + i], s);
            h = fmaf(hA[i * RANK + r], hB[r * N_FEAT + i], h);
        }
        g_scale[i] = s * 2.0f;   // SCALING = ALPHA/RANK = 8/4
        g_shift[i] = h * 2.0f;
    }
}

__global__ __launch_bounds__(TPB, 3)
void lora_ln_kernel(const float* __restrict__ x,
                    float* __restrict__ out,
                    int rows) {
    extern __shared__ float4 smem4[];                 // 2 * N_FEAT/4 float4 = 64 KB
    float4* s_scale = smem4;
    float4* s_shift = smem4 + N_FEAT / 4;
    __shared__ float red[2 * NWARPS];
    __shared__ float s_mean, s_rstd;

    // Load the per-feature affine vectors into shared once per CTA.
    const float4* gsc4 = reinterpret_cast<const float4*>(g_scale);
    const float4* gsh4 = reinterpret_cast<const float4*>(g_shift);
    for (int i = threadIdx.x; i < N_FEAT / 4; i += TPB) {
        s_scale[i] = gsc4[i];
        s_shift[i] = gsh4[i];
    }
    __syncthreads();

    const int lane = threadIdx.x & 31;
    const int warp = threadIdx.x >> 5;
    const float invN = 1.0f / (float)N_FEAT;

    for (int row = blockIdx.x; row < rows; row += gridDim.x) {
        const float4* xr = reinterpret_cast<const float4*>(x + (size_t)row * N_FEAT);
        float4*       orw = reinterpret_cast<float4*>(out + (size_t)row * N_FEAT);

        float4 v[V4T];
        float sum = 0.f, sq = 0.f;
#pragma unroll
        for (int j = 0; j < V4T; j++) {
            v[j] = __ldcs(&xr[threadIdx.x + j * TPB]);   // streaming: don't pollute L1
            sum += v[j].x + v[j].y + v[j].z + v[j].w;
            sq = fmaf(v[j].x, v[j].x, sq);
            sq = fmaf(v[j].y, v[j].y, sq);
            sq = fmaf(v[j].z, v[j].z, sq);
            sq = fmaf(v[j].w, v[j].w, sq);
        }

        // warp reduction
#pragma unroll
        for (int o = 16; o > 0; o >>= 1) {
            sum += __shfl_xor_sync(0xFFFFFFFFu, sum, o);
            sq  += __shfl_xor_sync(0xFFFFFFFFu, sq, o);
        }
        if (lane == 0) { red[2 * warp] = sum; red[2 * warp + 1] = sq; }
        __syncthreads();

        // block reduction (warp 0)
        if (warp == 0) {
            float a = (lane < NWARPS) ? red[2 * lane]     : 0.f;
            float b = (lane < NWARPS) ? red[2 * lane + 1] : 0.f;
#pragma unroll
            for (int o = NWARPS / 2; o > 0; o >>= 1) {
                a += __shfl_xor_sync(0xFFFFFFFFu, a, o);
                b += __shfl_xor_sync(0xFFFFFFFFu, b, o);
            }
            if (lane == 0) {
                float mean = a * invN;
                float var  = fmaf(-mean, mean, b * invN);
                s_mean = mean;
                s_rstd = rsqrtf(var + EPS_LN);
            }
        }
        __syncthreads();

        const float mean = s_mean;
        const float rstd = s_rstd;

#pragma unroll
        for (int j = 0; j < V4T; j++) {
            int i4 = threadIdx.x + j * TPB;
            float4 sc = s_scale[i4];
            float4 sh = s_shift[i4];
            float4 o;
            o.x = fmaf((v[j].x - mean) * rstd, sc.x, sh.x);
            o.y = fmaf((v[j].y - mean) * rstd, sc.y, sh.y);
            o.z = fmaf((v[j].z - mean) * rstd, sc.z, sh.z);
            o.w = fmaf((v[j].w - mean) * rstd, sc.w, sh.w);
            __stcs(&orw[i4], o);
        }
        __syncthreads();   // protect red[] / s_mean for the next row
    }
}

extern "C" void kernel_launch(void* const* d_in, const int* in_sizes, int n_in,
                              void* d_out, int out_size) {
    const float* x  = (const float*)d_in[0];
    const float* sA = (const float*)d_in[1];
    const float* sB = (const float*)d_in[2];
    const float* hA = (const float*)d_in[3];
    const float* hB = (const float*)d_in[4];
    float* out = (float*)d_out;

    const int rows = in_sizes[0] / N_FEAT;           // 8192

    // Prologue: rank-4 diagonal contraction -> g_scale / g_shift.
    compute_scales_kernel<<<(N_FEAT + 255) / 256, 256>>>(sA, sB, hA, hB);

    // Main LN: persistent one-wave grid, 3 CTAs/SM * 148 SMs.
    const int smem_bytes = 2 * N_FEAT * sizeof(float);   // 64 KB dynamic
    static bool attr_set = false;
    (void)attr_set;
    cudaFuncSetAttribute(lora_ln_kernel,
                         cudaFuncAttributeMaxDynamicSharedMemorySize, smem_bytes);

    int grid = 148 * 3;
    if (grid > rows) grid = rows;
    lora_ln_kernel<<<grid, TPB, smem_bytes>>>(x, out, rows);
}